// round 7
// baseline (speedup 1.0000x reference)
#include <cuda_runtime.h>
#include <cuda_fp16.h>
#include <math.h>
#include <stdint.h>

// ===========================================================================
// LogicRecursiveNN on GB300 (plain sm_103 target -> mma.sync path).
// Single-pass fp16 GEMMs, f32 accumulate.
//   gemm_mma128 : 128x128 CTA, 256 thr, warp tile 64x32, KC=32, 4 stages
//   gemm_mmaW   : 128x256 CTA, 256 thr, warp tile 64x64, KC=64, 3 stages
// All weight transposes fused into one batched launch.
// ===========================================================================

#define B_    512
#define NT_   2
#define NL_   64
#define E_    512
#define T_    512

#define SA_   ((size_t)B_ * NT_ * NL_ * E_)
#define SB_   ((size_t)B_ * NT_ * NL_ * E_ / 2)
#define SH_   ((size_t)B_ * NT_ * (NL_/2) * 4 * E_)
#define SF_   ((size_t)B_ * (T_ + NT_ * E_))
#define SZ1_  ((size_t)B_ * E_)
#define SZ2_  ((size_t)B_ * (E_/2))
#define SZ3_  ((size_t)B_ * (E_/4))

__device__ __half g_bufA[SA_];
__device__ __half g_bufB[SB_];
__device__ __half g_bufH[SH_];
__device__ __half g_feat[SF_];
__device__ __half g_z1[SZ1_];
__device__ __half g_z2[SZ2_];
__device__ __half g_z3[SZ3_];
__device__ __half g_wT[6193152];

#define W1T_OFF  0          // [2048,1024]
#define W2T_OFF  2097152    // [512,2048]
#define O1T_OFF  3145728    // [2048,512]
#define O2T_OFF  4194304    // [512,2048]
#define H1T_OFF  5242880    // [512,1536]
#define H2T_OFF  6029312    // [256,512]
#define H3T_OFF  6160384    // [128,256]

// ---------------------------------------------------------------------------
// helpers
// ---------------------------------------------------------------------------
__device__ __forceinline__ uint32_t smem_u32(const void* p) {
    uint32_t a;
    asm("{ .reg .u64 t; cvta.to.shared.u64 t, %1; cvt.u32.u64 %0, t; }"
        : "=r"(a) : "l"(p));
    return a;
}
__device__ __forceinline__ void cp16(uint32_t dst, const void* src) {
    asm volatile("cp.async.cg.shared.global [%0], [%1], 16;"
                 :: "r"(dst), "l"(src) : "memory");
}
__device__ __forceinline__ void cp_commit() {
    asm volatile("cp.async.commit_group;" ::: "memory");
}
template <int N>
__device__ __forceinline__ void cp_wait() {
    asm volatile("cp.async.wait_group %0;" :: "n"(N) : "memory");
}
__device__ __forceinline__ void ldm_x4(uint32_t* r, uint32_t addr) {
    asm volatile("ldmatrix.sync.aligned.m8n8.x4.shared.b16 {%0,%1,%2,%3}, [%4];"
                 : "=r"(r[0]), "=r"(r[1]), "=r"(r[2]), "=r"(r[3]) : "r"(addr));
}
__device__ __forceinline__ void ldm_x2(uint32_t* r, uint32_t addr) {
    asm volatile("ldmatrix.sync.aligned.m8n8.x2.shared.b16 {%0,%1}, [%2];"
                 : "=r"(r[0]), "=r"(r[1]) : "r"(addr));
}
__device__ __forceinline__ void mma_f16(float* c, const uint32_t* a, const uint32_t* b) {
    asm volatile(
        "mma.sync.aligned.m16n8k16.row.col.f32.f16.f16.f32 "
        "{%0,%1,%2,%3}, {%4,%5,%6,%7}, {%8,%9}, {%0,%1,%2,%3};"
        : "+f"(c[0]), "+f"(c[1]), "+f"(c[2]), "+f"(c[3])
        : "r"(a[0]), "r"(a[1]), "r"(a[2]), "r"(a[3]), "r"(b[0]), "r"(b[1]));
}

#define ACT_RELU 0
#define ACT_TANH 1
template <int ACT>
__device__ __forceinline__ float apply_act(float x) {
    if (ACT == ACT_RELU) return fmaxf(x, 0.0f);
    return tanhf(x);
}

// ---------------------------------------------------------------------------
// small kernels
// ---------------------------------------------------------------------------
__global__ void gather_kernel(const int* __restrict__ idx,
                              const float* __restrict__ emb,
                              __half* __restrict__ out)
{
    const int row = blockIdx.x;
    const int e = idx[row];
    const float4 v = ((const float4*)(emb + (size_t)e * E_))[threadIdx.x];
    __half h[4];
    h[0] = __float2half_rn(v.x); h[1] = __float2half_rn(v.y);
    h[2] = __float2half_rn(v.z); h[3] = __float2half_rn(v.w);
    *(uint2*)(out + (size_t)row * E_ + threadIdx.x * 4) = *(uint2*)h;
}

// batched transpose: all 7 weight matrices in one launch
struct TransJobs {
    const float* W[7];
    __half* Wt[7];
    int K[7], N[7];
    int ofs[8];          // prefix sum of tile counts
};

__global__ void transpose_all(TransJobs jobs)
{
    __shared__ float t[32][33];
    // find job
    int j = 0;
#pragma unroll
    for (int q = 1; q < 7; q++) if ((int)blockIdx.x >= jobs.ofs[q]) j = q;
    const int tile = blockIdx.x - jobs.ofs[j];
    const int K = jobs.K[j], N = jobs.N[j];
    const int tilesX = N / 32;
    const int bx = (tile % tilesX) * 32;
    const int by = (tile / tilesX) * 32;
    const float* W = jobs.W[j];
    __half* Wt = jobs.Wt[j];

    for (int i = threadIdx.y; i < 32; i += 8)
        t[i][threadIdx.x] = W[(size_t)(by + i) * N + bx + threadIdx.x];
    __syncthreads();
    for (int i = threadIdx.y; i < 32; i += 8)
        Wt[(size_t)(bx + i) * K + by + threadIdx.x] = __float2half_rn(t[threadIdx.x][i]);
}

__global__ void feat_kernel(const float* __restrict__ th,
                            const __half* __restrict__ root2,
                            __half* __restrict__ feat)
{
    const int b = blockIdx.x;
    const int t = threadIdx.x;
    const size_t o = (size_t)b * (T_ + NT_ * E_) + t * 4;
    if (t < T_ / 4) {
        const float4 v = ((const float4*)th)[t];
        __half h[4];
        h[0] = __float2half_rn(v.x); h[1] = __float2half_rn(v.y);
        h[2] = __float2half_rn(v.z); h[3] = __float2half_rn(v.w);
        *(uint2*)(feat + o) = *(uint2*)h;
    } else {
        *(uint2*)(feat + o) =
            *(const uint2*)(root2 + (size_t)b * (NT_ * E_) + (t - T_ / 4) * 4);
    }
}

__global__ void final_kernel(const __half* __restrict__ z3,
                             const float* __restrict__ w,
                             const float* __restrict__ b0,
                             float* __restrict__ out)
{
    const int warp = (blockIdx.x * blockDim.x + threadIdx.x) >> 5;
    const int lane = threadIdx.x & 31;
    if (warp >= B_) return;
    const size_t base = (size_t)warp * 128;
    float s = 0.0f;
#pragma unroll
    for (int i = lane; i < 128; i += 32)
        s = fmaf(__half2float(z3[base + i]), w[i], s);
#pragma unroll
    for (int o = 16; o > 0; o >>= 1) s += __shfl_down_sync(0xFFFFFFFFu, s, o);
    if (lane == 0) {
        const float x = s + b0[0];
        out[warp] = 1.0f / (1.0f + expf(-x));
    }
}

// ---------------------------------------------------------------------------
// gemm_mma128: 128x128 CTA, 8 warps (2x4), warp tile 64x32, KC=32, 4 stages
// ---------------------------------------------------------------------------
#define KC       32
#define PITCH    80
#define STG4     4
#define TILE128  (128 * PITCH)
#define STAGE128 (2 * TILE128)
#define GSMEM128 (STG4 * STAGE128)           // 81920

template <int ACT>
__global__ void __launch_bounds__(256, 1)
gemm_mma128(const __half* __restrict__ A,
            const __half* __restrict__ Bt,
            const float* __restrict__ bias,
            __half* __restrict__ C,
            int M, int N, int K)
{
    extern __shared__ char smem[];
    const uint32_t sb = smem_u32(smem);
    const int tid = threadIdx.x;
    const int wid = tid >> 5;
    const int lane = tid & 31;
    const int wm = wid >> 2;
    const int wn = wid & 3;

    const size_t row0 = (size_t)blockIdx.y * 128;
    const size_t col0 = (size_t)blockIdx.x * 128;
    const __half* Ag = A + row0 * K;
    const __half* Bg = Bt + col0 * K;

    const int seg = tid & 3;
    const int rowc = tid >> 2;

    const int nk = K / KC;

#pragma unroll
    for (int c = 0; c < STG4 - 1; c++) {
        if (c < nk) {
            const uint32_t st = sb + c * STAGE128;
            const int k0 = c * KC;
#pragma unroll
            for (int h = 0; h < 2; h++) {
                const int r = rowc + h * 64;
                const size_t go = (size_t)r * K + k0 + seg * 8;
                const uint32_t so = r * PITCH + seg * 16;
                cp16(st + so, Ag + go);
                cp16(st + TILE128 + so, Bg + go);
            }
        }
        cp_commit();
    }

    float acc[4][4][4];
#pragma unroll
    for (int i = 0; i < 4; i++)
#pragma unroll
        for (int j = 0; j < 4; j++)
#pragma unroll
            for (int k = 0; k < 4; k++) acc[i][j][k] = 0.0f;

    const uint32_t aoff = (uint32_t)((wm * 64 + (lane & 15)) * PITCH + (lane >> 4) * 16);
    const uint32_t boff = (uint32_t)((wn * 32 + (lane & 7)) * PITCH + ((lane >> 3) & 1) * 16);

    for (int i = 0; i < nk; i++) {
        cp_wait<STG4 - 2>();
        __syncthreads();

        // issue next stage first (overlaps with compute below)
        const int c = i + STG4 - 1;
        if (c < nk) {
            const uint32_t stw = sb + (c % STG4) * STAGE128;
            const int k0 = c * KC;
#pragma unroll
            for (int h = 0; h < 2; h++) {
                const int r = rowc + h * 64;
                const size_t go = (size_t)r * K + k0 + seg * 8;
                const uint32_t so = r * PITCH + seg * 16;
                cp16(stw + so, Ag + go);
                cp16(stw + TILE128 + so, Bg + go);
            }
        }
        cp_commit();

        const uint32_t st = sb + (i % STG4) * STAGE128;
        const uint32_t aB = st + aoff;
        const uint32_t bB = st + TILE128 + boff;

#pragma unroll
        for (int ks = 0; ks < 2; ks++) {
            uint32_t af[4][4], bf[4][2];
#pragma unroll
            for (int mt = 0; mt < 4; mt++) ldm_x4(af[mt], aB + mt * (16 * PITCH) + ks * 32);
#pragma unroll
            for (int nt = 0; nt < 4; nt++) ldm_x2(bf[nt], bB + nt * (8 * PITCH) + ks * 32);
#pragma unroll
            for (int mt = 0; mt < 4; mt++)
#pragma unroll
                for (int nt = 0; nt < 4; nt++) mma_f16(acc[mt][nt], af[mt], bf[nt]);
        }
    }

    const int lr = lane >> 2;
    const int lc = (lane & 3) * 2;
#pragma unroll
    for (int mt = 0; mt < 4; mt++) {
#pragma unroll
        for (int nt = 0; nt < 4; nt++) {
            const size_t r0 = row0 + wm * 64 + mt * 16 + lr;
            const size_t cc = col0 + wn * 32 + nt * 8 + lc;
            const float bx = __ldg(bias + cc);
            const float by = __ldg(bias + cc + 1);
#pragma unroll
            for (int hh = 0; hh < 2; hh++) {
                const size_t r = r0 + hh * 8;
                __half hp[2];
                hp[0] = __float2half_rn(apply_act<ACT>(acc[mt][nt][hh * 2 + 0] + bx));
                hp[1] = __float2half_rn(apply_act<ACT>(acc[mt][nt][hh * 2 + 1] + by));
                *(uint32_t*)(C + r * N + cc) = *(uint32_t*)hp;
            }
        }
    }
}

// ---------------------------------------------------------------------------
// gemm_mmaW: 128x256 CTA, 256 threads, warp tile 64x64, KC=64, 3 stages
// ---------------------------------------------------------------------------
#define KCW      64
#define PITCHW   144                         // 64 fp16 (128B) + 16B pad
#define STGW     3
#define TILE_AW  (128 * PITCHW)              // 18432
#define TILE_BW  (256 * PITCHW)              // 36864
#define STAGEW   (TILE_AW + TILE_BW)         // 55296
#define GSMEMW   (STGW * STAGEW)             // 165888

template <int ACT>
__global__ void __launch_bounds__(256, 1)
gemm_mmaW(const __half* __restrict__ A,
          const __half* __restrict__ Bt,
          const float* __restrict__ bias,
          __half* __restrict__ C,
          int M, int N, int K)
{
    extern __shared__ char smem[];
    const uint32_t sb = smem_u32(smem);
    const int tid = threadIdx.x;
    const int wid = tid >> 5;
    const int lane = tid & 31;
    const int wm = wid >> 2;        // 0..1
    const int wn = wid & 3;         // 0..3

    const size_t row0 = (size_t)blockIdx.y * 128;
    const size_t col0 = (size_t)blockIdx.x * 256;
    const __half* Ag = A + row0 * K;
    const __half* Bg = Bt + col0 * K;

    const int seg = tid & 7;        // 16B chunk within 128B row
    const int rowc = tid >> 3;      // 0..31

    const int nk = K / KCW;

#pragma unroll
    for (int c = 0; c < STGW - 1; c++) {
        if (c < nk) {
            const uint32_t st = sb + c * STAGEW;
            const int k0 = c * KCW;
#pragma unroll
            for (int h = 0; h < 4; h++) {
                const int r = rowc + h * 32;
                cp16(st + r * PITCHW + seg * 16, Ag + (size_t)r * K + k0 + seg * 8);
            }
#pragma unroll
            for (int h = 0; h < 8; h++) {
                const int r = rowc + h * 32;
                cp16(st + TILE_AW + r * PITCHW + seg * 16, Bg + (size_t)r * K + k0 + seg * 8);
            }
        }
        cp_commit();
    }

    float acc[4][8][4];
#pragma unroll
    for (int i = 0; i < 4; i++)
#pragma unroll
        for (int j = 0; j < 8; j++)
#pragma unroll
            for (int k = 0; k < 4; k++) acc[i][j][k] = 0.0f;

    const uint32_t aoff = (uint32_t)((wm * 64 + (lane & 15)) * PITCHW + (lane >> 4) * 16);
    const uint32_t boff = (uint32_t)((wn * 64 + (lane & 7) + ((lane >> 4) << 3)) * PITCHW
                                     + ((lane >> 3) & 1) * 16);

    for (int i = 0; i < nk; i++) {
        cp_wait<STGW - 2>();
        __syncthreads();

        // issue next stage before compute
        const int c = i + STGW - 1;
        if (c < nk) {
            const uint32_t stw = sb + (c % STGW) * STAGEW;
            const int k0 = c * KCW;
#pragma unroll
            for (int h = 0; h < 4; h++) {
                const int r = rowc + h * 32;
                cp16(stw + r * PITCHW + seg * 16, Ag + (size_t)r * K + k0 + seg * 8);
            }
#pragma unroll
            for (int h = 0; h < 8; h++) {
                const int r = rowc + h * 32;
                cp16(stw + TILE_AW + r * PITCHW + seg * 16, Bg + (size_t)r * K + k0 + seg * 8);
            }
        }
        cp_commit();

        const uint32_t st = sb + (i % STGW) * STAGEW;
        const uint32_t aB = st + aoff;
        const uint32_t bB = st + TILE_AW + boff;

#pragma unroll
        for (int ks = 0; ks < 4; ks++) {
            uint32_t af[4][4], bf[4][4];
#pragma unroll
            for (int mt = 0; mt < 4; mt++) ldm_x4(af[mt], aB + mt * (16 * PITCHW) + ks * 32);
#pragma unroll
            for (int nt2 = 0; nt2 < 4; nt2++) ldm_x4(bf[nt2], bB + nt2 * (16 * PITCHW) + ks * 32);
#pragma unroll
            for (int mt = 0; mt < 4; mt++)
#pragma unroll
                for (int nt2 = 0; nt2 < 4; nt2++) {
                    mma_f16(acc[mt][2 * nt2 + 0], af[mt], &bf[nt2][0]);
                    mma_f16(acc[mt][2 * nt2 + 1], af[mt], &bf[nt2][2]);
                }
        }
    }

    const int lr = lane >> 2;
    const int lc = (lane & 3) * 2;
#pragma unroll
    for (int mt = 0; mt < 4; mt++) {
#pragma unroll
        for (int nt = 0; nt < 8; nt++) {
            const size_t r0 = row0 + wm * 64 + mt * 16 + lr;
            const size_t cc = col0 + wn * 64 + nt * 8 + lc;
            const float bx = __ldg(bias + cc);
            const float by = __ldg(bias + cc + 1);
#pragma unroll
            for (int hh = 0; hh < 2; hh++) {
                const size_t r = r0 + hh * 8;
                __half hp[2];
                hp[0] = __float2half_rn(apply_act<ACT>(acc[mt][nt][hh * 2 + 0] + bx));
                hp[1] = __float2half_rn(apply_act<ACT>(acc[mt][nt][hh * 2 + 1] + by));
                *(uint32_t*)(C + r * N + cc) = *(uint32_t*)hp;
            }
        }
    }
}

// ---------------------------------------------------------------------------
// launch
// ---------------------------------------------------------------------------
static void launch_gemm(int act, const __half* A, const __half* Bt,
                        const float* bias, __half* C, int M, int N, int K)
{
    const bool wide = (N % 256 == 0) && (M % 128 == 0) && (K % 64 == 0) &&
                      ((M / 128) * (N / 256) >= 120);
    if (wide) {
        dim3 g(N / 256, M / 128);
        if (act == ACT_RELU)
            gemm_mmaW<ACT_RELU><<<g, 256, GSMEMW>>>(A, Bt, bias, C, M, N, K);
        else
            gemm_mmaW<ACT_TANH><<<g, 256, GSMEMW>>>(A, Bt, bias, C, M, N, K);
    } else {
        dim3 g(N / 128, M / 128);
        if (act == ACT_RELU)
            gemm_mma128<ACT_RELU><<<g, 256, GSMEM128>>>(A, Bt, bias, C, M, N, K);
        else
            gemm_mma128<ACT_TANH><<<g, 256, GSMEM128>>>(A, Bt, bias, C, M, N, K);
    }
}

extern "C" void kernel_launch(void* const* d_in, const int* in_sizes, int n_in,
                              void* d_out, int out_size)
{
    const int*   leaf = (const int*)  d_in[0];
    const float* ent  = (const float*)d_in[1];
    const float* th   = (const float*)d_in[2];
    const float* w1   = (const float*)d_in[3];
    const float* b1   = (const float*)d_in[4];
    const float* w2   = (const float*)d_in[5];
    const float* b2   = (const float*)d_in[6];
    const float* o1   = (const float*)d_in[7];
    const float* ob1  = (const float*)d_in[8];
    const float* o2   = (const float*)d_in[9];
    const float* ob2  = (const float*)d_in[10];
    const float* h1   = (const float*)d_in[11];
    const float* hb1  = (const float*)d_in[12];
    const float* h2   = (const float*)d_in[13];
    const float* hb2  = (const float*)d_in[14];
    const float* h3   = (const float*)d_in[15];
    const float* hb3  = (const float*)d_in[16];
    const float* h4   = (const float*)d_in[17];
    const float* hb4  = (const float*)d_in[18];

    __half *bufA, *bufB, *H, *feat, *z1, *z2, *z3, *wT;
    cudaGetSymbolAddress((void**)&bufA, g_bufA);
    cudaGetSymbolAddress((void**)&bufB, g_bufB);
    cudaGetSymbolAddress((void**)&H,    g_bufH);
    cudaGetSymbolAddress((void**)&feat, g_feat);
    cudaGetSymbolAddress((void**)&z1,   g_z1);
    cudaGetSymbolAddress((void**)&z2,   g_z2);
    cudaGetSymbolAddress((void**)&z3,   g_z3);
    cudaGetSymbolAddress((void**)&wT,   g_wT);

    cudaFuncSetAttribute(gemm_mma128<ACT_RELU>,
                         cudaFuncAttributeMaxDynamicSharedMemorySize, GSMEM128);
    cudaFuncSetAttribute(gemm_mma128<ACT_TANH>,
                         cudaFuncAttributeMaxDynamicSharedMemorySize, GSMEM128);
    cudaFuncSetAttribute(gemm_mmaW<ACT_RELU>,
                         cudaFuncAttributeMaxDynamicSharedMemorySize, GSMEMW);
    cudaFuncSetAttribute(gemm_mmaW<ACT_TANH>,
                         cudaFuncAttributeMaxDynamicSharedMemorySize, GSMEMW);

    // 0) fused weight transposes -> fp16 [N,K]
    {
        TransJobs jobs;
        const float* Ws[7]  = {w1, w2, o1, o2, h1, h2, h3};
        __half* Wts[7] = {wT + W1T_OFF, wT + W2T_OFF, wT + O1T_OFF, wT + O2T_OFF,
                          wT + H1T_OFF, wT + H2T_OFF, wT + H3T_OFF};
        const int Ks[7] = {2 * E_, 4 * E_, E_, 4 * E_, T_ + NT_ * E_, E_, E_ / 2};
        const int Ns[7] = {4 * E_, E_, 4 * E_, E_, E_, E_ / 2, E_ / 4};
        int acc = 0;
        for (int j = 0; j < 7; j++) {
            jobs.W[j] = Ws[j]; jobs.Wt[j] = Wts[j];
            jobs.K[j] = Ks[j]; jobs.N[j] = Ns[j];
            jobs.ofs[j] = acc;
            acc += (Ns[j] / 32) * (Ks[j] / 32);
        }
        jobs.ofs[7] = acc;
        transpose_all<<<acc, dim3(32, 8)>>>(jobs);
    }

    // 1) leaf gather
    gather_kernel<<<B_ * NT_ * NL_, E_ / 4>>>(leaf, ent, bufA);

    // 2) tree reduction (6 levels)
    __half* in  = bufA;
    __half* out = bufB;
    int n = NL_;
    while (n > 1) {
        const int rows = B_ * NT_ * (n / 2);
        launch_gemm(ACT_RELU, in, wT + W1T_OFF, b1, H, rows, 4 * E_, 2 * E_);
        launch_gemm(ACT_RELU, H, wT + W2T_OFF, b2, out, rows, E_, 4 * E_);
        __half* tp = in; in = out; out = tp;
        n >>= 1;
    }

    // 3) one2one
    {
        const int rows = B_ * NT_;
        launch_gemm(ACT_RELU, in, wT + O1T_OFF, ob1, H, rows, 4 * E_, E_);
        launch_gemm(ACT_TANH, H, wT + O2T_OFF, ob2, out, rows, E_, 4 * E_);
    }

    // 4) feat = [th | root2]
    feat_kernel<<<B_, (T_ + NT_ * E_) / 4>>>(th, out, feat);

    // 5) head
    launch_gemm(ACT_RELU, feat, wT + H1T_OFF, hb1, z1, B_, E_, T_ + NT_ * E_);
    launch_gemm(ACT_RELU, z1, wT + H2T_OFF, hb2, z2, B_, E_ / 2, E_);
    launch_gemm(ACT_RELU, z2, wT + H3T_OFF, hb3, z3, B_, E_ / 4, E_ / 2);

    // 6) final dot + sigmoid
    final_kernel<<<(B_ * 32 + 255) / 256, 256>>>(z3, h4, hb4, (float*)d_out);
}

// round 8
// speedup vs baseline: 1.0540x; 1.0540x over previous
#include <cuda_runtime.h>
#include <cuda_fp16.h>
#include <math.h>
#include <stdint.h>

// ===========================================================================
// LogicRecursiveNN on GB300 (plain sm_103 target -> mma.sync path).
// Single-pass fp16 GEMMs, f32 accumulate.
// ONE gemm kernel: 128x128 CTA, 256 thr, 8 warps (2x4), warp tile 64x32,
// KC=32, 4 stages, __launch_bounds__(256,2) -> regs<=128 -> 2 CTAs/SM.
// Two resident CTAs give two independent barrier domains per SM: one CTA's
// mainloop barrier stall is covered by the other CTA's MMA issue.
// ===========================================================================

#define B_    512
#define NT_   2
#define NL_   64
#define E_    512
#define T_    512

#define SA_   ((size_t)B_ * NT_ * NL_ * E_)
#define SB_   ((size_t)B_ * NT_ * NL_ * E_ / 2)
#define SH_   ((size_t)B_ * NT_ * (NL_/2) * 4 * E_)
#define SF_   ((size_t)B_ * (T_ + NT_ * E_))
#define SZ1_  ((size_t)B_ * E_)
#define SZ2_  ((size_t)B_ * (E_/2))
#define SZ3_  ((size_t)B_ * (E_/4))

__device__ __half g_bufA[SA_];
__device__ __half g_bufB[SB_];
__device__ __half g_bufH[SH_];
__device__ __half g_feat[SF_];
__device__ __half g_z1[SZ1_];
__device__ __half g_z2[SZ2_];
__device__ __half g_z3[SZ3_];
__device__ __half g_wT[6193152];

#define W1T_OFF  0          // [2048,1024]
#define W2T_OFF  2097152    // [512,2048]
#define O1T_OFF  3145728    // [2048,512]
#define O2T_OFF  4194304    // [512,2048]
#define H1T_OFF  5242880    // [512,1536]
#define H2T_OFF  6029312    // [256,512]
#define H3T_OFF  6160384    // [128,256]

// ---------------------------------------------------------------------------
// helpers
// ---------------------------------------------------------------------------
__device__ __forceinline__ uint32_t smem_u32(const void* p) {
    uint32_t a;
    asm("{ .reg .u64 t; cvta.to.shared.u64 t, %1; cvt.u32.u64 %0, t; }"
        : "=r"(a) : "l"(p));
    return a;
}
__device__ __forceinline__ void cp16(uint32_t dst, const void* src) {
    asm volatile("cp.async.cg.shared.global [%0], [%1], 16;"
                 :: "r"(dst), "l"(src) : "memory");
}
__device__ __forceinline__ void cp_commit() {
    asm volatile("cp.async.commit_group;" ::: "memory");
}
template <int N>
__device__ __forceinline__ void cp_wait() {
    asm volatile("cp.async.wait_group %0;" :: "n"(N) : "memory");
}
__device__ __forceinline__ void ldm_x4(uint32_t* r, uint32_t addr) {
    asm volatile("ldmatrix.sync.aligned.m8n8.x4.shared.b16 {%0,%1,%2,%3}, [%4];"
                 : "=r"(r[0]), "=r"(r[1]), "=r"(r[2]), "=r"(r[3]) : "r"(addr));
}
__device__ __forceinline__ void ldm_x2(uint32_t* r, uint32_t addr) {
    asm volatile("ldmatrix.sync.aligned.m8n8.x2.shared.b16 {%0,%1}, [%2];"
                 : "=r"(r[0]), "=r"(r[1]) : "r"(addr));
}
__device__ __forceinline__ void mma_f16(float* c, const uint32_t* a, const uint32_t* b) {
    asm volatile(
        "mma.sync.aligned.m16n8k16.row.col.f32.f16.f16.f32 "
        "{%0,%1,%2,%3}, {%4,%5,%6,%7}, {%8,%9}, {%0,%1,%2,%3};"
        : "+f"(c[0]), "+f"(c[1]), "+f"(c[2]), "+f"(c[3])
        : "r"(a[0]), "r"(a[1]), "r"(a[2]), "r"(a[3]), "r"(b[0]), "r"(b[1]));
}

#define ACT_RELU 0
#define ACT_TANH 1
template <int ACT>
__device__ __forceinline__ float apply_act(float x) {
    if (ACT == ACT_RELU) return fmaxf(x, 0.0f);
    return tanhf(x);
}

// ---------------------------------------------------------------------------
// small kernels
// ---------------------------------------------------------------------------
__global__ void gather_kernel(const int* __restrict__ idx,
                              const float* __restrict__ emb,
                              __half* __restrict__ out)
{
    const int row = blockIdx.x;
    const int e = idx[row];
    const float4 v = ((const float4*)(emb + (size_t)e * E_))[threadIdx.x];
    __half h[4];
    h[0] = __float2half_rn(v.x); h[1] = __float2half_rn(v.y);
    h[2] = __float2half_rn(v.z); h[3] = __float2half_rn(v.w);
    *(uint2*)(out + (size_t)row * E_ + threadIdx.x * 4) = *(uint2*)h;
}

struct TransJobs {
    const float* W[7];
    __half* Wt[7];
    int K[7], N[7];
    int ofs[8];
};

__global__ void transpose_all(TransJobs jobs)
{
    __shared__ float t[32][33];
    int j = 0;
#pragma unroll
    for (int q = 1; q < 7; q++) if ((int)blockIdx.x >= jobs.ofs[q]) j = q;
    const int tile = blockIdx.x - jobs.ofs[j];
    const int K = jobs.K[j], N = jobs.N[j];
    const int tilesX = N / 32;
    const int bx = (tile % tilesX) * 32;
    const int by = (tile / tilesX) * 32;
    const float* W = jobs.W[j];
    __half* Wt = jobs.Wt[j];

    for (int i = threadIdx.y; i < 32; i += 8)
        t[i][threadIdx.x] = W[(size_t)(by + i) * N + bx + threadIdx.x];
    __syncthreads();
    for (int i = threadIdx.y; i < 32; i += 8)
        Wt[(size_t)(bx + i) * K + by + threadIdx.x] = __float2half_rn(t[threadIdx.x][i]);
}

__global__ void feat_kernel(const float* __restrict__ th,
                            const __half* __restrict__ root2,
                            __half* __restrict__ feat)
{
    const int b = blockIdx.x;
    const int t = threadIdx.x;
    const size_t o = (size_t)b * (T_ + NT_ * E_) + t * 4;
    if (t < T_ / 4) {
        const float4 v = ((const float4*)th)[t];
        __half h[4];
        h[0] = __float2half_rn(v.x); h[1] = __float2half_rn(v.y);
        h[2] = __float2half_rn(v.z); h[3] = __float2half_rn(v.w);
        *(uint2*)(feat + o) = *(uint2*)h;
    } else {
        *(uint2*)(feat + o) =
            *(const uint2*)(root2 + (size_t)b * (NT_ * E_) + (t - T_ / 4) * 4);
    }
}

__global__ void final_kernel(const __half* __restrict__ z3,
                             const float* __restrict__ w,
                             const float* __restrict__ b0,
                             float* __restrict__ out)
{
    const int warp = (blockIdx.x * blockDim.x + threadIdx.x) >> 5;
    const int lane = threadIdx.x & 31;
    if (warp >= B_) return;
    const size_t base = (size_t)warp * 128;
    float s = 0.0f;
#pragma unroll
    for (int i = lane; i < 128; i += 32)
        s = fmaf(__half2float(z3[base + i]), w[i], s);
#pragma unroll
    for (int o = 16; o > 0; o >>= 1) s += __shfl_down_sync(0xFFFFFFFFu, s, o);
    if (lane == 0) {
        const float x = s + b0[0];
        out[warp] = 1.0f / (1.0f + expf(-x));
    }
}

// ---------------------------------------------------------------------------
// gemm_mma128: 128x128 CTA, 8 warps (2x4), warp tile 64x32, KC=32, 4 stages,
// 2 CTAs/SM (launch_bounds) -> two independent barrier domains per SM.
// ---------------------------------------------------------------------------
#define KC       32
#define PITCH    80
#define STG4     4
#define TILE128  (128 * PITCH)               // 10240
#define STAGE128 (2 * TILE128)               // 20480
#define GSMEM128 (STG4 * STAGE128)           // 81920 (x2 CTAs = 160 KB/SM)

template <int ACT>
__global__ void __launch_bounds__(256, 2)
gemm_mma128(const __half* __restrict__ A,
            const __half* __restrict__ Bt,
            const float* __restrict__ bias,
            __half* __restrict__ C,
            int M, int N, int K)
{
    extern __shared__ char smem[];
    const uint32_t sb = smem_u32(smem);
    const int tid = threadIdx.x;
    const int wid = tid >> 5;
    const int lane = tid & 31;
    const int wm = wid >> 2;
    const int wn = wid & 3;

    const size_t row0 = (size_t)blockIdx.y * 128;
    const size_t col0 = (size_t)blockIdx.x * 128;
    const __half* Ag = A + row0 * K;
    const __half* Bg = Bt + col0 * K;

    const int seg = tid & 3;
    const int rowc = tid >> 2;

    const int nk = K / KC;

#pragma unroll
    for (int c = 0; c < STG4 - 1; c++) {
        if (c < nk) {
            const uint32_t st = sb + c * STAGE128;
            const int k0 = c * KC;
#pragma unroll
            for (int h = 0; h < 2; h++) {
                const int r = rowc + h * 64;
                const size_t go = (size_t)r * K + k0 + seg * 8;
                const uint32_t so = r * PITCH + seg * 16;
                cp16(st + so, Ag + go);
                cp16(st + TILE128 + so, Bg + go);
            }
        }
        cp_commit();
    }

    float acc[4][4][4];
#pragma unroll
    for (int i = 0; i < 4; i++)
#pragma unroll
        for (int j = 0; j < 4; j++)
#pragma unroll
            for (int k = 0; k < 4; k++) acc[i][j][k] = 0.0f;

    const uint32_t aoff = (uint32_t)((wm * 64 + (lane & 15)) * PITCH + (lane >> 4) * 16);
    const uint32_t boff = (uint32_t)((wn * 32 + (lane & 7)) * PITCH + ((lane >> 3) & 1) * 16);

    for (int i = 0; i < nk; i++) {
        cp_wait<STG4 - 2>();
        __syncthreads();

        const uint32_t st = sb + (i % STG4) * STAGE128;
        const uint32_t aB = st + aoff;
        const uint32_t bB = st + TILE128 + boff;

#pragma unroll
        for (int ks = 0; ks < 2; ks++) {
            uint32_t af[4][4], bf[4][2];
#pragma unroll
            for (int mt = 0; mt < 4; mt++) ldm_x4(af[mt], aB + mt * (16 * PITCH) + ks * 32);
#pragma unroll
            for (int nt = 0; nt < 4; nt++) ldm_x2(bf[nt], bB + nt * (8 * PITCH) + ks * 32);
#pragma unroll
            for (int mt = 0; mt < 4; mt++)
#pragma unroll
                for (int nt = 0; nt < 4; nt++) mma_f16(acc[mt][nt], af[mt], bf[nt]);
        }

        const int c = i + STG4 - 1;
        if (c < nk) {
            const uint32_t stw = sb + (c % STG4) * STAGE128;
            const int k0 = c * KC;
#pragma unroll
            for (int h = 0; h < 2; h++) {
                const int r = rowc + h * 64;
                const size_t go = (size_t)r * K + k0 + seg * 8;
                const uint32_t so = r * PITCH + seg * 16;
                cp16(stw + so, Ag + go);
                cp16(stw + TILE128 + so, Bg + go);
            }
        }
        cp_commit();
    }

    const int lr = lane >> 2;
    const int lc = (lane & 3) * 2;
#pragma unroll
    for (int mt = 0; mt < 4; mt++) {
#pragma unroll
        for (int nt = 0; nt < 4; nt++) {
            const size_t r0 = row0 + wm * 64 + mt * 16 + lr;
            const size_t cc = col0 + wn * 32 + nt * 8 + lc;
            const float bx = __ldg(bias + cc);
            const float by = __ldg(bias + cc + 1);
#pragma unroll
            for (int hh = 0; hh < 2; hh++) {
                const size_t r = r0 + hh * 8;
                __half hp[2];
                hp[0] = __float2half_rn(apply_act<ACT>(acc[mt][nt][hh * 2 + 0] + bx));
                hp[1] = __float2half_rn(apply_act<ACT>(acc[mt][nt][hh * 2 + 1] + by));
                *(uint32_t*)(C + r * N + cc) = *(uint32_t*)hp;
            }
        }
    }
}

// ---------------------------------------------------------------------------
// launch
// ---------------------------------------------------------------------------
static void launch_gemm(int act, const __half* A, const __half* Bt,
                        const float* bias, __half* C, int M, int N, int K)
{
    dim3 g(N / 128, M / 128);
    if (act == ACT_RELU)
        gemm_mma128<ACT_RELU><<<g, 256, GSMEM128>>>(A, Bt, bias, C, M, N, K);
    else
        gemm_mma128<ACT_TANH><<<g, 256, GSMEM128>>>(A, Bt, bias, C, M, N, K);
}

extern "C" void kernel_launch(void* const* d_in, const int* in_sizes, int n_in,
                              void* d_out, int out_size)
{
    const int*   leaf = (const int*)  d_in[0];
    const float* ent  = (const float*)d_in[1];
    const float* th   = (const float*)d_in[2];
    const float* w1   = (const float*)d_in[3];
    const float* b1   = (const float*)d_in[4];
    const float* w2   = (const float*)d_in[5];
    const float* b2   = (const float*)d_in[6];
    const float* o1   = (const float*)d_in[7];
    const float* ob1  = (const float*)d_in[8];
    const float* o2   = (const float*)d_in[9];
    const float* ob2  = (const float*)d_in[10];
    const float* h1   = (const float*)d_in[11];
    const float* hb1  = (const float*)d_in[12];
    const float* h2   = (const float*)d_in[13];
    const float* hb2  = (const float*)d_in[14];
    const float* h3   = (const float*)d_in[15];
    const float* hb3  = (const float*)d_in[16];
    const float* h4   = (const float*)d_in[17];
    const float* hb4  = (const float*)d_in[18];

    __half *bufA, *bufB, *H, *feat, *z1, *z2, *z3, *wT;
    cudaGetSymbolAddress((void**)&bufA, g_bufA);
    cudaGetSymbolAddress((void**)&bufB, g_bufB);
    cudaGetSymbolAddress((void**)&H,    g_bufH);
    cudaGetSymbolAddress((void**)&feat, g_feat);
    cudaGetSymbolAddress((void**)&z1,   g_z1);
    cudaGetSymbolAddress((void**)&z2,   g_z2);
    cudaGetSymbolAddress((void**)&z3,   g_z3);
    cudaGetSymbolAddress((void**)&wT,   g_wT);

    cudaFuncSetAttribute(gemm_mma128<ACT_RELU>,
                         cudaFuncAttributeMaxDynamicSharedMemorySize, GSMEM128);
    cudaFuncSetAttribute(gemm_mma128<ACT_TANH>,
                         cudaFuncAttributeMaxDynamicSharedMemorySize, GSMEM128);

    // 0) fused weight transposes -> fp16 [N,K]
    {
        TransJobs jobs;
        const float* Ws[7]  = {w1, w2, o1, o2, h1, h2, h3};
        __half* Wts[7] = {wT + W1T_OFF, wT + W2T_OFF, wT + O1T_OFF, wT + O2T_OFF,
                          wT + H1T_OFF, wT + H2T_OFF, wT + H3T_OFF};
        const int Ks[7] = {2 * E_, 4 * E_, E_, 4 * E_, T_ + NT_ * E_, E_, E_ / 2};
        const int Ns[7] = {4 * E_, E_, 4 * E_, E_, E_, E_ / 2, E_ / 4};
        int acc = 0;
        for (int j = 0; j < 7; j++) {
            jobs.W[j] = Ws[j]; jobs.Wt[j] = Wts[j];
            jobs.K[j] = Ks[j]; jobs.N[j] = Ns[j];
            jobs.ofs[j] = acc;
            acc += (Ns[j] / 32) * (Ks[j] / 32);
        }
        jobs.ofs[7] = acc;
        transpose_all<<<acc, dim3(32, 8)>>>(jobs);
    }

    // 1) leaf gather
    gather_kernel<<<B_ * NT_ * NL_, E_ / 4>>>(leaf, ent, bufA);

    // 2) tree reduction (6 levels)
    __half* in  = bufA;
    __half* out = bufB;
    int n = NL_;
    while (n > 1) {
        const int rows = B_ * NT_ * (n / 2);
        launch_gemm(ACT_RELU, in, wT + W1T_OFF, b1, H, rows, 4 * E_, 2 * E_);
        launch_gemm(ACT_RELU, H, wT + W2T_OFF, b2, out, rows, E_, 4 * E_);
        __half* tp = in; in = out; out = tp;
        n >>= 1;
    }

    // 3) one2one
    {
        const int rows = B_ * NT_;
        launch_gemm(ACT_RELU, in, wT + O1T_OFF, ob1, H, rows, 4 * E_, E_);
        launch_gemm(ACT_TANH, H, wT + O2T_OFF, ob2, out, rows, E_, 4 * E_);
    }

    // 4) feat = [th | root2]
    feat_kernel<<<B_, (T_ + NT_ * E_) / 4>>>(th, out, feat);

    // 5) head
    launch_gemm(ACT_RELU, feat, wT + H1T_OFF, hb1, z1, B_, E_, T_ + NT_ * E_);
    launch_gemm(ACT_RELU, z1, wT + H2T_OFF, hb2, z2, B_, E_ / 2, E_);
    launch_gemm(ACT_RELU, z2, wT + H3T_OFF, hb3, z3, B_, E_ / 4, E_ / 2);

    // 6) final dot + sigmoid
    final_kernel<<<(B_ * 32 + 255) / 256, 256>>>(z3, h4, hb4, (float*)d_out);
}

// round 9
// speedup vs baseline: 1.1827x; 1.1221x over previous
#include <cuda_runtime.h>
#include <cuda_fp16.h>
#include <math.h>
#include <stdint.h>

// ===========================================================================
// LogicRecursiveNN on GB300 (plain sm_103 target -> mma.sync path).
// Single-pass fp16 GEMMs, f32 accumulate.
// GEMM: 128x128 CTA, 128 threads (4 warps, 2x2), warp tile 64x64, KC=32,
// 4 stages, __launch_bounds__(128,2) -> 2 CTAs/SM, <=256 regs/thread.
// Rationale: smem-crossbar-bound at 64x32 warp tiles (0.047 B/FLOP needs
// 192 B/cyc > 128 available). 64x64 tiles cut operand traffic to 0.031 B/FLOP.
// ===========================================================================

#define B_    512
#define NT_   2
#define NL_   64
#define E_    512
#define T_    512

#define SA_   ((size_t)B_ * NT_ * NL_ * E_)
#define SB_   ((size_t)B_ * NT_ * NL_ * E_ / 2)
#define SH_   ((size_t)B_ * NT_ * (NL_/2) * 4 * E_)
#define SF_   ((size_t)B_ * (T_ + NT_ * E_))
#define SZ1_  ((size_t)B_ * E_)
#define SZ2_  ((size_t)B_ * (E_/2))
#define SZ3_  ((size_t)B_ * (E_/4))

__device__ __half g_bufA[SA_];
__device__ __half g_bufB[SB_];
__device__ __half g_bufH[SH_];
__device__ __half g_feat[SF_];
__device__ __half g_z1[SZ1_];
__device__ __half g_z2[SZ2_];
__device__ __half g_z3[SZ3_];
__device__ __half g_wT[6193152];

#define W1T_OFF  0          // [2048,1024]
#define W2T_OFF  2097152    // [512,2048]
#define O1T_OFF  3145728    // [2048,512]
#define O2T_OFF  4194304    // [512,2048]
#define H1T_OFF  5242880    // [512,1536]
#define H2T_OFF  6029312    // [256,512]
#define H3T_OFF  6160384    // [128,256]

// ---------------------------------------------------------------------------
// helpers
// ---------------------------------------------------------------------------
__device__ __forceinline__ uint32_t smem_u32(const void* p) {
    uint32_t a;
    asm("{ .reg .u64 t; cvta.to.shared.u64 t, %1; cvt.u32.u64 %0, t; }"
        : "=r"(a) : "l"(p));
    return a;
}
__device__ __forceinline__ void cp16(uint32_t dst, const void* src) {
    asm volatile("cp.async.cg.shared.global [%0], [%1], 16;"
                 :: "r"(dst), "l"(src) : "memory");
}
__device__ __forceinline__ void cp_commit() {
    asm volatile("cp.async.commit_group;" ::: "memory");
}
template <int N>
__device__ __forceinline__ void cp_wait() {
    asm volatile("cp.async.wait_group %0;" :: "n"(N) : "memory");
}
__device__ __forceinline__ void ldm_x4(uint32_t* r, uint32_t addr) {
    asm volatile("ldmatrix.sync.aligned.m8n8.x4.shared.b16 {%0,%1,%2,%3}, [%4];"
                 : "=r"(r[0]), "=r"(r[1]), "=r"(r[2]), "=r"(r[3]) : "r"(addr));
}
__device__ __forceinline__ void mma_f16(float* c, const uint32_t* a, const uint32_t* b) {
    asm volatile(
        "mma.sync.aligned.m16n8k16.row.col.f32.f16.f16.f32 "
        "{%0,%1,%2,%3}, {%4,%5,%6,%7}, {%8,%9}, {%0,%1,%2,%3};"
        : "+f"(c[0]), "+f"(c[1]), "+f"(c[2]), "+f"(c[3])
        : "r"(a[0]), "r"(a[1]), "r"(a[2]), "r"(a[3]), "r"(b[0]), "r"(b[1]));
}

#define ACT_RELU 0
#define ACT_TANH 1
template <int ACT>
__device__ __forceinline__ float apply_act(float x) {
    if (ACT == ACT_RELU) return fmaxf(x, 0.0f);
    return tanhf(x);
}

// ---------------------------------------------------------------------------
// small kernels
// ---------------------------------------------------------------------------
__global__ void gather_kernel(const int* __restrict__ idx,
                              const float* __restrict__ emb,
                              __half* __restrict__ out)
{
    const int row = blockIdx.x;
    const int e = idx[row];
    const float4 v = ((const float4*)(emb + (size_t)e * E_))[threadIdx.x];
    __half h[4];
    h[0] = __float2half_rn(v.x); h[1] = __float2half_rn(v.y);
    h[2] = __float2half_rn(v.z); h[3] = __float2half_rn(v.w);
    *(uint2*)(out + (size_t)row * E_ + threadIdx.x * 4) = *(uint2*)h;
}

struct TransJobs {
    const float* W[7];
    __half* Wt[7];
    int K[7], N[7];
    int ofs[8];
};

__global__ void transpose_all(TransJobs jobs)
{
    __shared__ float t[32][33];
    int j = 0;
#pragma unroll
    for (int q = 1; q < 7; q++) if ((int)blockIdx.x >= jobs.ofs[q]) j = q;
    const int tile = blockIdx.x - jobs.ofs[j];
    const int K = jobs.K[j], N = jobs.N[j];
    const int tilesX = N / 32;
    const int bx = (tile % tilesX) * 32;
    const int by = (tile / tilesX) * 32;
    const float* W = jobs.W[j];
    __half* Wt = jobs.Wt[j];

    for (int i = threadIdx.y; i < 32; i += 8)
        t[i][threadIdx.x] = W[(size_t)(by + i) * N + bx + threadIdx.x];
    __syncthreads();
    for (int i = threadIdx.y; i < 32; i += 8)
        Wt[(size_t)(bx + i) * K + by + threadIdx.x] = __float2half_rn(t[threadIdx.x][i]);
}

__global__ void feat_kernel(const float* __restrict__ th,
                            const __half* __restrict__ root2,
                            __half* __restrict__ feat)
{
    const int b = blockIdx.x;
    const int t = threadIdx.x;
    const size_t o = (size_t)b * (T_ + NT_ * E_) + t * 4;
    if (t < T_ / 4) {
        const float4 v = ((const float4*)th)[t];
        __half h[4];
        h[0] = __float2half_rn(v.x); h[1] = __float2half_rn(v.y);
        h[2] = __float2half_rn(v.z); h[3] = __float2half_rn(v.w);
        *(uint2*)(feat + o) = *(uint2*)h;
    } else {
        *(uint2*)(feat + o) =
            *(const uint2*)(root2 + (size_t)b * (NT_ * E_) + (t - T_ / 4) * 4);
    }
}

__global__ void final_kernel(const __half* __restrict__ z3,
                             const float* __restrict__ w,
                             const float* __restrict__ b0,
                             float* __restrict__ out)
{
    const int warp = (blockIdx.x * blockDim.x + threadIdx.x) >> 5;
    const int lane = threadIdx.x & 31;
    if (warp >= B_) return;
    const size_t base = (size_t)warp * 128;
    float s = 0.0f;
#pragma unroll
    for (int i = lane; i < 128; i += 32)
        s = fmaf(__half2float(z3[base + i]), w[i], s);
#pragma unroll
    for (int o = 16; o > 0; o >>= 1) s += __shfl_down_sync(0xFFFFFFFFu, s, o);
    if (lane == 0) {
        const float x = s + b0[0];
        out[warp] = 1.0f / (1.0f + expf(-x));
    }
}

// ---------------------------------------------------------------------------
// gemm_mma: 128x128 CTA, 128 threads (4 warps, 2x2), warp tile 64x64,
// KC=32, 4 stages, 2 CTAs/SM.
// ---------------------------------------------------------------------------
#define KC       32
#define PITCH    80
#define STG4     4
#define TILE128  (128 * PITCH)               // 10240
#define STAGE128 (2 * TILE128)               // 20480
#define GSMEM128 (STG4 * STAGE128)           // 81920 (x2 CTAs = 160 KB/SM)

template <int ACT>
__global__ void __launch_bounds__(128, 2)
gemm_mma(const __half* __restrict__ A,
         const __half* __restrict__ Bt,
         const float* __restrict__ bias,
         __half* __restrict__ C,
         int M, int N, int K)
{
    extern __shared__ char smem[];
    const uint32_t sb = smem_u32(smem);
    const int tid = threadIdx.x;
    const int wid = tid >> 5;
    const int lane = tid & 31;
    const int wm = wid >> 1;        // 0..1
    const int wn = wid & 1;         // 0..1

    const size_t row0 = (size_t)blockIdx.y * 128;
    const size_t col0 = (size_t)blockIdx.x * 128;
    const __half* Ag = A + row0 * K;
    const __half* Bg = Bt + col0 * K;

    const int seg = tid & 3;        // 16B chunk within 64B row
    const int rowc = tid >> 2;      // 0..31

    const int nk = K / KC;

#pragma unroll
    for (int c = 0; c < STG4 - 1; c++) {
        if (c < nk) {
            const uint32_t st = sb + c * STAGE128;
            const int k0 = c * KC;
#pragma unroll
            for (int h = 0; h < 4; h++) {
                const int r = rowc + h * 32;
                const size_t go = (size_t)r * K + k0 + seg * 8;
                const uint32_t so = r * PITCH + seg * 16;
                cp16(st + so, Ag + go);
                cp16(st + TILE128 + so, Bg + go);
            }
        }
        cp_commit();
    }

    float acc[4][8][4];
#pragma unroll
    for (int i = 0; i < 4; i++)
#pragma unroll
        for (int j = 0; j < 8; j++)
#pragma unroll
            for (int k = 0; k < 4; k++) acc[i][j][k] = 0.0f;

    const uint32_t aoff = (uint32_t)((wm * 64 + (lane & 15)) * PITCH + (lane >> 4) * 16);
    // B x4: covers n16 x k16 -> two n8 fragments
    const uint32_t boff = (uint32_t)((wn * 64 + (lane & 7) + ((lane >> 4) << 3)) * PITCH
                                     + ((lane >> 3) & 1) * 16);

    for (int i = 0; i < nk; i++) {
        cp_wait<STG4 - 2>();
        __syncthreads();

        const uint32_t st = sb + (i % STG4) * STAGE128;
        const uint32_t aB = st + aoff;
        const uint32_t bB = st + TILE128 + boff;

#pragma unroll
        for (int ks = 0; ks < 2; ks++) {
            uint32_t af[4][4], bf[4][4];
#pragma unroll
            for (int mt = 0; mt < 4; mt++) ldm_x4(af[mt], aB + mt * (16 * PITCH) + ks * 32);
#pragma unroll
            for (int nt2 = 0; nt2 < 4; nt2++) ldm_x4(bf[nt2], bB + nt2 * (16 * PITCH) + ks * 32);
#pragma unroll
            for (int mt = 0; mt < 4; mt++)
#pragma unroll
                for (int nt2 = 0; nt2 < 4; nt2++) {
                    mma_f16(acc[mt][2 * nt2 + 0], af[mt], &bf[nt2][0]);
                    mma_f16(acc[mt][2 * nt2 + 1], af[mt], &bf[nt2][2]);
                }
        }

        const int c = i + STG4 - 1;
        if (c < nk) {
            const uint32_t stw = sb + (c % STG4) * STAGE128;
            const int k0 = c * KC;
#pragma unroll
            for (int h = 0; h < 4; h++) {
                const int r = rowc + h * 32;
                const size_t go = (size_t)r * K + k0 + seg * 8;
                const uint32_t so = r * PITCH + seg * 16;
                cp16(stw + so, Ag + go);
                cp16(stw + TILE128 + so, Bg + go);
            }
        }
        cp_commit();
    }

    const int lr = lane >> 2;
    const int lc = (lane & 3) * 2;
#pragma unroll
    for (int mt = 0; mt < 4; mt++) {
#pragma unroll
        for (int nt = 0; nt < 8; nt++) {
            const size_t r0 = row0 + wm * 64 + mt * 16 + lr;
            const size_t cc = col0 + wn * 64 + nt * 8 + lc;
            const float bx = __ldg(bias + cc);
            const float by = __ldg(bias + cc + 1);
#pragma unroll
            for (int hh = 0; hh < 2; hh++) {
                const size_t r = r0 + hh * 8;
                __half hp[2];
                hp[0] = __float2half_rn(apply_act<ACT>(acc[mt][nt][hh * 2 + 0] + bx));
                hp[1] = __float2half_rn(apply_act<ACT>(acc[mt][nt][hh * 2 + 1] + by));
                *(uint32_t*)(C + r * N + cc) = *(uint32_t*)hp;
            }
        }
    }
}

// ---------------------------------------------------------------------------
// launch
// ---------------------------------------------------------------------------
static void launch_gemm(int act, const __half* A, const __half* Bt,
                        const float* bias, __half* C, int M, int N, int K)
{
    dim3 g(N / 128, M / 128);
    if (act == ACT_RELU)
        gemm_mma<ACT_RELU><<<g, 128, GSMEM128>>>(A, Bt, bias, C, M, N, K);
    else
        gemm_mma<ACT_TANH><<<g, 128, GSMEM128>>>(A, Bt, bias, C, M, N, K);
}

extern "C" void kernel_launch(void* const* d_in, const int* in_sizes, int n_in,
                              void* d_out, int out_size)
{
    const int*   leaf = (const int*)  d_in[0];
    const float* ent  = (const float*)d_in[1];
    const float* th   = (const float*)d_in[2];
    const float* w1   = (const float*)d_in[3];
    const float* b1   = (const float*)d_in[4];
    const float* w2   = (const float*)d_in[5];
    const float* b2   = (const float*)d_in[6];
    const float* o1   = (const float*)d_in[7];
    const float* ob1  = (const float*)d_in[8];
    const float* o2   = (const float*)d_in[9];
    const float* ob2  = (const float*)d_in[10];
    const float* h1   = (const float*)d_in[11];
    const float* hb1  = (const float*)d_in[12];
    const float* h2   = (const float*)d_in[13];
    const float* hb2  = (const float*)d_in[14];
    const float* h3   = (const float*)d_in[15];
    const float* hb3  = (const float*)d_in[16];
    const float* h4   = (const float*)d_in[17];
    const float* hb4  = (const float*)d_in[18];

    __half *bufA, *bufB, *H, *feat, *z1, *z2, *z3, *wT;
    cudaGetSymbolAddress((void**)&bufA, g_bufA);
    cudaGetSymbolAddress((void**)&bufB, g_bufB);
    cudaGetSymbolAddress((void**)&H,    g_bufH);
    cudaGetSymbolAddress((void**)&feat, g_feat);
    cudaGetSymbolAddress((void**)&z1,   g_z1);
    cudaGetSymbolAddress((void**)&z2,   g_z2);
    cudaGetSymbolAddress((void**)&z3,   g_z3);
    cudaGetSymbolAddress((void**)&wT,   g_wT);

    cudaFuncSetAttribute(gemm_mma<ACT_RELU>,
                         cudaFuncAttributeMaxDynamicSharedMemorySize, GSMEM128);
    cudaFuncSetAttribute(gemm_mma<ACT_TANH>,
                         cudaFuncAttributeMaxDynamicSharedMemorySize, GSMEM128);

    // 0) fused weight transposes -> fp16 [N,K]
    {
        TransJobs jobs;
        const float* Ws[7]  = {w1, w2, o1, o2, h1, h2, h3};
        __half* Wts[7] = {wT + W1T_OFF, wT + W2T_OFF, wT + O1T_OFF, wT + O2T_OFF,
                          wT + H1T_OFF, wT + H2T_OFF, wT + H3T_OFF};
        const int Ks[7] = {2 * E_, 4 * E_, E_, 4 * E_, T_ + NT_ * E_, E_, E_ / 2};
        const int Ns[7] = {4 * E_, E_, 4 * E_, E_, E_, E_ / 2, E_ / 4};
        int acc = 0;
        for (int j = 0; j < 7; j++) {
            jobs.W[j] = Ws[j]; jobs.Wt[j] = Wts[j];
            jobs.K[j] = Ks[j]; jobs.N[j] = Ns[j];
            jobs.ofs[j] = acc;
            acc += (Ns[j] / 32) * (Ks[j] / 32);
        }
        jobs.ofs[7] = acc;
        transpose_all<<<acc, dim3(32, 8)>>>(jobs);
    }

    // 1) leaf gather
    gather_kernel<<<B_ * NT_ * NL_, E_ / 4>>>(leaf, ent, bufA);

    // 2) tree reduction (6 levels)
    __half* in  = bufA;
    __half* out = bufB;
    int n = NL_;
    while (n > 1) {
        const int rows = B_ * NT_ * (n / 2);
        launch_gemm(ACT_RELU, in, wT + W1T_OFF, b1, H, rows, 4 * E_, 2 * E_);
        launch_gemm(ACT_RELU, H, wT + W2T_OFF, b2, out, rows, E_, 4 * E_);
        __half* tp = in; in = out; out = tp;
        n >>= 1;
    }

    // 3) one2one
    {
        const int rows = B_ * NT_;
        launch_gemm(ACT_RELU, in, wT + O1T_OFF, ob1, H, rows, 4 * E_, E_);
        launch_gemm(ACT_TANH, H, wT + O2T_OFF, ob2, out, rows, E_, 4 * E_);
    }

    // 4) feat = [th | root2]
    feat_kernel<<<B_, (T_ + NT_ * E_) / 4>>>(th, out, feat);

    // 5) head
    launch_gemm(ACT_RELU, feat, wT + H1T_OFF, hb1, z1, B_, E_, T_ + NT_ * E_);
    launch_gemm(ACT_RELU, z1, wT + H2T_OFF, hb2, z2, B_, E_ / 2, E_);
    launch_gemm(ACT_RELU, z2, wT + H3T_OFF, hb3, z3, B_, E_ / 4, E_ / 2);

    // 6) final dot + sigmoid
    final_kernel<<<(B_ * 32 + 255) / 256, 256>>>(z3, h4, hb4, (float*)d_out);
}